// round 8
// baseline (speedup 1.0000x reference)
#include <cuda_runtime.h>
#include <cuda_bf16.h>
#include <cstdint>

// Problem constants (fixed by the dataset)
#define K_DIM 256
#define N_DIM 64
#define MAX_NODES 100000
#define MAX_EDGES 1310720
#define SCAN_BLK 1024
#define MAX_SCAN_BLOCKS ((MAX_NODES + SCAN_BLK - 1) / SCAN_BLK + 2)

// Device scratch (no cudaMalloc allowed)
__device__ float g_pre[(size_t)MAX_NODES * N_DIM];          // X @ W
__device__ int g_idx64;                                      // index dtype flag
__device__ int g_row_cnt[MAX_NODES];                         // counts, then cursor
__device__ int g_row_off[MAX_NODES + 1];                     // CSR offsets
__device__ unsigned long long g_edge_cv[MAX_EDGES];          // packed (val,col)
__device__ int g_scan_part[MAX_SCAN_BLOCKS];                 // scan partials

// ===========================================================================
// detect index dtype. int64 values < 2^31 have zero high words.
// ===========================================================================
__global__ void detect_idx_kernel(const unsigned int* __restrict__ rows_u32, int E)
{
    __shared__ int any_nonzero;
    if (threadIdx.x == 0) any_nonzero = 0;
    __syncthreads();
    int n = E < 4096 ? E : 4096;
    for (int i = threadIdx.x; i < n; i += blockDim.x)
        if (rows_u32[2 * i + 1] != 0u) any_nonzero = 1;   // benign smem race
    __syncthreads();
    if (threadIdx.x == 0) g_idx64 = any_nonzero ? 0 : 1;
}

__device__ __forceinline__ int load_idx(const void* p, int e)
{
    return g_idx64 ? (int)((const long long*)p)[e] : ((const int*)p)[e];
}

// ===========================================================================
// GEMM  pre_sup[M,64] = X[M,256] @ W[256,64] via single-pass tf32 mma.sync.
// m16n8k8: thread (q=lane>>2, t=lane&3):
//   A row-major: a0=(q,t) a1=(q+8,t) a2=(q,t+4) a3=(q+8,t+4)
//   B col-major: b0=(k=t,n=q) b1=(k=t+4,n=q)
//   D: c0=(q,2t) c1=(q,2t+1) c2=(q+8,2t) c3=(q+8,2t+1)
// W staged per K-half (128 k) in smem, tf32, linear in k:
//   ws[n*WS4 + klocal], stride 132 u32 (528B == 16 mod 128 -> conflict-free).
// ===========================================================================
#define WS4 132   // u32 per n-row

__device__ __forceinline__ uint32_t f2tf32(float f)
{
    uint32_t r;
    asm("cvt.rna.tf32.f32 %0, %1;" : "=r"(r) : "f"(f));
    return r;
}

__device__ __forceinline__ void mma_tf32(float* d, uint32_t a0, uint32_t a1,
                                         uint32_t a2, uint32_t a3,
                                         uint32_t b0, uint32_t b1)
{
    asm volatile(
        "mma.sync.aligned.m16n8k8.row.col.f32.tf32.tf32.f32 "
        "{%0, %1, %2, %3}, {%4, %5, %6, %7}, {%8, %9}, {%0, %1, %2, %3};"
        : "+f"(d[0]), "+f"(d[1]), "+f"(d[2]), "+f"(d[3])
        : "r"(a0), "r"(a1), "r"(a2), "r"(a3), "r"(b0), "r"(b1));
}

__global__ void __launch_bounds__(256) gemm_mma_kernel(
    const float* __restrict__ x, const float* __restrict__ w, int M)
{
    __shared__ uint32_t ws[64 * WS4];   // 33792 B

    const int tid  = threadIdx.x;
    const int wid  = tid >> 5;
    const int lane = tid & 31;
    const int q = lane >> 2;
    const int t = lane & 3;

    const int warp_m = blockIdx.x * 128 + wid * 16;
    const int row0 = warp_m + q;
    const int row1 = row0 + 8;
    const int row0c = row0 < M ? row0 : 0;
    const int row1c = row1 < M ? row1 : 0;
    const float* xr0 = x + (size_t)row0c * K_DIM;
    const float* xr1 = x + (size_t)row1c * K_DIM;

    float acc[8][4];
#pragma unroll
    for (int j = 0; j < 8; j++)
#pragma unroll
        for (int i = 0; i < 4; i++) acc[j][i] = 0.f;

    // prime A pipeline (global kstep 0)
    float a0 = xr0[t], a1 = xr1[t], a2 = xr0[t + 4], a3 = xr1[t + 4];

#pragma unroll 1
    for (int stage = 0; stage < 2; stage++) {
        // ---- stage W K-half into smem as tf32 (coalesced over n)
#pragma unroll 1
        for (int idx = tid; idx < 8192; idx += 256) {
            int n  = idx & 63;
            int kl = idx >> 6;   // 0..127
            ws[n * WS4 + kl] = f2tf32(w[(size_t)(stage * 128 + kl) * N_DIM + n]);
        }
        __syncthreads();

#pragma unroll 1
        for (int ks = 0; ks < 16; ks++) {
            const int gks = stage * 16 + ks;
            // prefetch next kstep's A (wraps to 0 on last; discarded)
            const int k0n = (gks < 31) ? (gks + 1) * 8 : 0;
            float n0 = xr0[k0n + t];
            float n1 = xr1[k0n + t];
            float n2 = xr0[k0n + t + 4];
            float n3 = xr1[k0n + t + 4];

            uint32_t A0 = f2tf32(a0), A1 = f2tf32(a1);
            uint32_t A2 = f2tf32(a2), A3 = f2tf32(a3);

#pragma unroll
            for (int j = 0; j < 8; j++) {
                const int n = j * 8 + q;
                uint32_t b0 = ws[n * WS4 + ks * 8 + t];
                uint32_t b1 = ws[n * WS4 + ks * 8 + 4 + t];
                mma_tf32(acc[j], A0, A1, A2, A3, b0, b1);
            }
            a0 = n0; a1 = n1; a2 = n2; a3 = n3;
        }
        __syncthreads();
    }

#pragma unroll
    for (int j = 0; j < 8; j++) {
        int c = j * 8 + 2 * t;
        if (row0 < M)
            *(float2*)(g_pre + (size_t)row0 * N_DIM + c) =
                make_float2(acc[j][0], acc[j][1]);
        if (row1 < M)
            *(float2*)(g_pre + (size_t)row1 * N_DIM + c) =
                make_float2(acc[j][2], acc[j][3]);
    }
}

// ===========================================================================
// CSR build
// ===========================================================================
__global__ void zero_cnt_kernel(int N)
{
    int i = blockIdx.x * blockDim.x + threadIdx.x;
    if (i < N) g_row_cnt[i] = 0;
}

__global__ void hist_kernel(const void* __restrict__ rows_p, int E)
{
    int e = blockIdx.x * blockDim.x + threadIdx.x;
    if (e >= E) return;
    atomicAdd(&g_row_cnt[load_idx(rows_p, e)], 1);
}

// scan step 1: per-block sums of counts
__global__ void __launch_bounds__(SCAN_BLK) scan_partial_kernel(int N)
{
    __shared__ int warp_sums[32];
    int idx = blockIdx.x * SCAN_BLK + threadIdx.x;
    int v = (idx < N) ? g_row_cnt[idx] : 0;
#pragma unroll
    for (int o = 16; o > 0; o >>= 1) v += __shfl_down_sync(0xffffffffu, v, o);
    if ((threadIdx.x & 31) == 0) warp_sums[threadIdx.x >> 5] = v;
    __syncthreads();
    if (threadIdx.x < 32) {
        int s = warp_sums[threadIdx.x];
#pragma unroll
        for (int o = 16; o > 0; o >>= 1) s += __shfl_down_sync(0xffffffffu, s, o);
        if (threadIdx.x == 0) g_scan_part[blockIdx.x] = s;
    }
}

// scan step 2: serial exclusive scan of block partials (tiny)
__global__ void scan_base_kernel(int nblocks, int N)
{
    if (threadIdx.x == 0 && blockIdx.x == 0) {
        int run = 0;
        for (int b = 0; b < nblocks; b++) {
            int t = g_scan_part[b];
            g_scan_part[b] = run;
            run += t;
        }
        g_row_off[N] = run;   // = E
    }
}

// scan step 3: block-local exclusive scan + base -> offsets and cursor
__global__ void __launch_bounds__(SCAN_BLK) scan_write_kernel(int N)
{
    __shared__ int warp_sums[32];
    int idx = blockIdx.x * SCAN_BLK + threadIdx.x;
    int lane = threadIdx.x & 31;
    int wid = threadIdx.x >> 5;

    int v = (idx < N) ? g_row_cnt[idx] : 0;
    int incl = v;
#pragma unroll
    for (int o = 1; o < 32; o <<= 1) {
        int n = __shfl_up_sync(0xffffffffu, incl, o);
        if (lane >= o) incl += n;
    }
    if (lane == 31) warp_sums[wid] = incl;
    __syncthreads();
    if (wid == 0) {
        int s = (lane < 32) ? warp_sums[lane] : 0;
#pragma unroll
        for (int o = 1; o < 32; o <<= 1) {
            int n = __shfl_up_sync(0xffffffffu, s, o);
            if (lane >= o) s += n;
        }
        warp_sums[lane] = s;
    }
    __syncthreads();
    int warp_base = (wid == 0) ? 0 : warp_sums[wid - 1];
    int excl = g_scan_part[blockIdx.x] + warp_base + incl - v;
    if (idx < N) {
        g_row_off[idx] = excl;
        g_row_cnt[idx] = excl;   // becomes the permute cursor
    }
}

// permute: scatter (col,val) into row-sorted list
__global__ void permute_kernel(const void* __restrict__ rows_p,
                               const void* __restrict__ cols_p,
                               const float* __restrict__ vals, int E)
{
    int e = blockIdx.x * blockDim.x + threadIdx.x;
    if (e >= E) return;
    int r = load_idx(rows_p, e);
    int c = load_idx(cols_p, e);
    unsigned int v = __float_as_uint(vals[e]);
    int pos = atomicAdd(&g_row_cnt[r], 1);
    g_edge_cv[pos] = ((unsigned long long)v << 32) | (unsigned int)c;
}

// ===========================================================================
// Gather-reduce: out[r,:] = relu( sum_e val*pre_sup[col,:] + bias )
// 16 threads per row; unrolled by 2 with dual accumulators for MLP.
// ===========================================================================
__global__ void __launch_bounds__(256) gather_kernel(
    const float* __restrict__ bias, float* __restrict__ out, int N)
{
    int r = blockIdx.x * 16 + (threadIdx.x >> 4);
    int q = threadIdx.x & 15;
    if (r >= N) return;

    int i   = g_row_off[r];
    int end = g_row_off[r + 1];

    float4 acc0 = make_float4(0.f, 0.f, 0.f, 0.f);
    float4 acc1 = make_float4(0.f, 0.f, 0.f, 0.f);
    for (; i + 2 <= end; i += 2) {
        unsigned long long cv0 = g_edge_cv[i];
        unsigned long long cv1 = g_edge_cv[i + 1];
        int c0 = (int)(unsigned int)cv0;
        int c1 = (int)(unsigned int)cv1;
        float v0 = __uint_as_float((unsigned int)(cv0 >> 32));
        float v1 = __uint_as_float((unsigned int)(cv1 >> 32));
        float4 p0 = *(const float4*)(g_pre + (size_t)c0 * N_DIM + q * 4);
        float4 p1 = *(const float4*)(g_pre + (size_t)c1 * N_DIM + q * 4);
        acc0.x = fmaf(v0, p0.x, acc0.x);
        acc0.y = fmaf(v0, p0.y, acc0.y);
        acc0.z = fmaf(v0, p0.z, acc0.z);
        acc0.w = fmaf(v0, p0.w, acc0.w);
        acc1.x = fmaf(v1, p1.x, acc1.x);
        acc1.y = fmaf(v1, p1.y, acc1.y);
        acc1.z = fmaf(v1, p1.z, acc1.z);
        acc1.w = fmaf(v1, p1.w, acc1.w);
    }
    if (i < end) {
        unsigned long long cv = g_edge_cv[i];
        int c   = (int)(unsigned int)cv;
        float v = __uint_as_float((unsigned int)(cv >> 32));
        float4 p = *(const float4*)(g_pre + (size_t)c * N_DIM + q * 4);
        acc0.x = fmaf(v, p.x, acc0.x);
        acc0.y = fmaf(v, p.y, acc0.y);
        acc0.z = fmaf(v, p.z, acc0.z);
        acc0.w = fmaf(v, p.w, acc0.w);
    }

    float4 b = *(const float4*)(bias + q * 4);
    float4 o;
    o.x = fmaxf(acc0.x + acc1.x + b.x, 0.f);
    o.y = fmaxf(acc0.y + acc1.y + b.y, 0.f);
    o.z = fmaxf(acc0.z + acc1.z + b.z, 0.f);
    o.w = fmaxf(acc0.w + acc1.w + b.w, 0.f);
    *(float4*)(out + (size_t)r * N_DIM + q * 4) = o;
}

// ===========================================================================
// Launch — ordered so the GEMM is the 4th node (ncu captures launch #4).
// Inputs: 0:x f32[N,256]  1:rows i32/i64[E]  2:cols i32/i64[E]
//         3:vals f32[E]   4:weight f32[256,64]  5:bias f32[64]
// Output: f32 [N, 64]
// ===========================================================================
extern "C" void kernel_launch(void* const* d_in, const int* in_sizes, int n_in,
                              void* d_out, int out_size)
{
    const float* x    = (const float*)d_in[0];
    const void*  rows = d_in[1];
    const void*  cols = d_in[2];
    const float* vals = (const float*)d_in[3];
    const float* w    = (const float*)d_in[4];
    const float* bias = (const float*)d_in[5];
    float*       out  = (float*)d_out;

    const int N = in_sizes[0] / K_DIM;
    const int E = in_sizes[1];
    const int scan_blocks = (N + SCAN_BLK - 1) / SCAN_BLK;

    zero_cnt_kernel<<<(N + 1023) / 1024, 1024>>>(N);                     // 1
    detect_idx_kernel<<<1, 1024>>>((const unsigned int*)rows, E);        // 2
    hist_kernel<<<(E + 511) / 512, 512>>>(rows, E);                      // 3
    gemm_mma_kernel<<<(N + 127) / 128, 256>>>(x, w, N);                  // 4 <- profiled
    scan_partial_kernel<<<scan_blocks, SCAN_BLK>>>(N);                   // 5
    scan_base_kernel<<<1, 32>>>(scan_blocks, N);                         // 6
    scan_write_kernel<<<scan_blocks, SCAN_BLK>>>(N);                     // 7
    permute_kernel<<<(E + 511) / 512, 512>>>(rows, cols, vals, E);       // 8
    gather_kernel<<<(N + 15) / 16, 256>>>(bias, out, N);                 // 9
}

// round 9
// speedup vs baseline: 1.1726x; 1.1726x over previous
#include <cuda_runtime.h>
#include <cuda_bf16.h>
#include <cstdint>

// Problem constants (fixed by the dataset)
#define K_DIM 256
#define N_DIM 64
#define MAX_NODES 100000
#define MAX_EDGES 1310720
#define SCAN_BLK 1024
#define MAX_SCAN_BLOCKS ((MAX_NODES + SCAN_BLK - 1) / SCAN_BLK + 2)

// Device scratch (no cudaMalloc allowed)
__device__ float g_pre[(size_t)MAX_NODES * N_DIM];          // X @ W
__device__ int g_idx64;                                      // index dtype flag
__device__ int g_row_cnt[MAX_NODES];                         // counts, then cursor
__device__ int g_row_off[MAX_NODES + 1];                     // CSR offsets
__device__ unsigned long long g_edge_cv[MAX_EDGES];          // packed (val,col)
__device__ int g_scan_part[MAX_SCAN_BLOCKS];                 // scan partials

// ===========================================================================
// detect index dtype. int64 values < 2^31 have zero high words.
// ===========================================================================
__global__ void detect_idx_kernel(const unsigned int* __restrict__ rows_u32, int E)
{
    __shared__ int any_nonzero;
    if (threadIdx.x == 0) any_nonzero = 0;
    __syncthreads();
    int n = E < 4096 ? E : 4096;
    for (int i = threadIdx.x; i < n; i += blockDim.x)
        if (rows_u32[2 * i + 1] != 0u) any_nonzero = 1;   // benign smem race
    __syncthreads();
    if (threadIdx.x == 0) g_idx64 = any_nonzero ? 0 : 1;
}

__device__ __forceinline__ int load_idx(const void* p, int e)
{
    return g_idx64 ? (int)((const long long*)p)[e] : ((const int*)p)[e];
}

// ===========================================================================
// GEMM  pre_sup[M,64] = X[M,256] @ W[256,64] via tf32 mma.sync (m16n8k8),
// X staged through smem with fully coalesced float4 loads (the R8 profile
// showed the GEMM bound at 1.2TB/s effective DRAM from 8-line LDG replays).
//
// Per CTA: 256 threads, 8 warps, M-tile 128; loop over 8 K-slabs of 32.
//   xs[m][kl] stride 36 floats: frag reads bank = (4m+kl)%32, lanes (q,t)
//     -> 4q+t all-distinct => conflict-free.
//   wb[n][kl] stride 36 u32 : frag reads bank 4q+t-based, conflict-free.
// m16n8k8 frags, thread (q=lane>>2, t=lane&3):
//   A row-major: a0=(q,kt) a1=(q+8,kt) a2=(q,kt+4) a3=(q+8,kt+4)
//   B col-major: b0=(k=kt,n) b1=(k=kt+4,n);  D: (q,2t),(q,2t+1),(q+8,..)
// ===========================================================================
#define XS_STRIDE 36
#define WB_STRIDE 36

__device__ __forceinline__ uint32_t f2tf32(float f)
{
    uint32_t r;
    asm("cvt.rna.tf32.f32 %0, %1;" : "=r"(r) : "f"(f));
    return r;
}

__device__ __forceinline__ void mma_tf32(float* d, uint32_t a0, uint32_t a1,
                                         uint32_t a2, uint32_t a3,
                                         uint32_t b0, uint32_t b1)
{
    asm volatile(
        "mma.sync.aligned.m16n8k8.row.col.f32.tf32.tf32.f32 "
        "{%0, %1, %2, %3}, {%4, %5, %6, %7}, {%8, %9}, {%0, %1, %2, %3};"
        : "+f"(d[0]), "+f"(d[1]), "+f"(d[2]), "+f"(d[3])
        : "r"(a0), "r"(a1), "r"(a2), "r"(a3), "r"(b0), "r"(b1));
}

__global__ void __launch_bounds__(256) gemm_mma_kernel(
    const float* __restrict__ x, const float* __restrict__ w, int M)
{
    __shared__ float    xs[128 * XS_STRIDE];   // 18432 B
    __shared__ uint32_t wb[64 * WB_STRIDE];    //  9216 B

    const int tid  = threadIdx.x;
    const int wid  = tid >> 5;
    const int lane = tid & 31;
    const int q = lane >> 2;
    const int t = lane & 3;

    const int mbase = blockIdx.x * 128;
    const int r0l = wid * 16 + q;        // local row of a0/a2
    const int r1l = r0l + 8;             // local row of a1/a3
    const int row0 = mbase + r0l;
    const int row1 = mbase + r1l;

    float acc[8][4];
#pragma unroll
    for (int j = 0; j < 8; j++)
#pragma unroll
        for (int i = 0; i < 4; i++) acc[j][i] = 0.f;

#pragma unroll 1
    for (int s = 0; s < 8; s++) {
        // ---- stage X slab: 128 rows x 32 k, coalesced float4
#pragma unroll
        for (int i = 0; i < 4; i++) {
            int f4 = i * 256 + tid;          // 0..1023
            int m  = f4 >> 3;                // local row
            int c  = (f4 & 7) * 4;           // k offset in slab
            int gm = mbase + m;
            float4 v = make_float4(0.f, 0.f, 0.f, 0.f);
            if (gm < M)
                v = *(const float4*)(x + (size_t)gm * K_DIM + s * 32 + c);
            *(float4*)&xs[m * XS_STRIDE + c] = v;
        }
        // ---- stage W slab: 32 k x 64 n, tf32 (coalesced over n)
#pragma unroll
        for (int i = 0; i < 8; i++) {
            int idx = i * 256 + tid;         // 0..2047
            int n  = idx & 63;
            int kl = idx >> 6;               // 0..31
            wb[n * WB_STRIDE + kl] = f2tf32(w[(size_t)(s * 32 + kl) * N_DIM + n]);
        }
        __syncthreads();

#pragma unroll
        for (int ks = 0; ks < 4; ks++) {
            const int kt = ks * 8 + t;
            uint32_t A0 = f2tf32(xs[r0l * XS_STRIDE + kt]);
            uint32_t A1 = f2tf32(xs[r1l * XS_STRIDE + kt]);
            uint32_t A2 = f2tf32(xs[r0l * XS_STRIDE + kt + 4]);
            uint32_t A3 = f2tf32(xs[r1l * XS_STRIDE + kt + 4]);
#pragma unroll
            for (int j = 0; j < 8; j++) {
                const int n = j * 8 + q;
                uint32_t b0 = wb[n * WB_STRIDE + kt];
                uint32_t b1 = wb[n * WB_STRIDE + kt + 4];
                mma_tf32(acc[j], A0, A1, A2, A3, b0, b1);
            }
        }
        __syncthreads();
    }

#pragma unroll
    for (int j = 0; j < 8; j++) {
        int c = j * 8 + 2 * t;
        if (row0 < M)
            *(float2*)(g_pre + (size_t)row0 * N_DIM + c) =
                make_float2(acc[j][0], acc[j][1]);
        if (row1 < M)
            *(float2*)(g_pre + (size_t)row1 * N_DIM + c) =
                make_float2(acc[j][2], acc[j][3]);
    }
}

// ===========================================================================
// CSR build
// ===========================================================================
__global__ void zero_cnt_kernel(int N)
{
    int i = blockIdx.x * blockDim.x + threadIdx.x;
    if (i < N) g_row_cnt[i] = 0;
}

__global__ void hist_kernel(const void* __restrict__ rows_p, int E)
{
    int e = blockIdx.x * blockDim.x + threadIdx.x;
    if (e >= E) return;
    atomicAdd(&g_row_cnt[load_idx(rows_p, e)], 1);
}

// scan step 1: per-block sums of counts
__global__ void __launch_bounds__(SCAN_BLK) scan_partial_kernel(int N)
{
    __shared__ int warp_sums[32];
    int idx = blockIdx.x * SCAN_BLK + threadIdx.x;
    int v = (idx < N) ? g_row_cnt[idx] : 0;
#pragma unroll
    for (int o = 16; o > 0; o >>= 1) v += __shfl_down_sync(0xffffffffu, v, o);
    if ((threadIdx.x & 31) == 0) warp_sums[threadIdx.x >> 5] = v;
    __syncthreads();
    if (threadIdx.x < 32) {
        int s = warp_sums[threadIdx.x];
#pragma unroll
        for (int o = 16; o > 0; o >>= 1) s += __shfl_down_sync(0xffffffffu, s, o);
        if (threadIdx.x == 0) g_scan_part[blockIdx.x] = s;
    }
}

// scan step 2: serial exclusive scan of block partials (tiny)
__global__ void scan_base_kernel(int nblocks, int N)
{
    if (threadIdx.x == 0 && blockIdx.x == 0) {
        int run = 0;
        for (int b = 0; b < nblocks; b++) {
            int t = g_scan_part[b];
            g_scan_part[b] = run;
            run += t;
        }
        g_row_off[N] = run;   // = E
    }
}

// scan step 3: block-local exclusive scan + base -> offsets and cursor
__global__ void __launch_bounds__(SCAN_BLK) scan_write_kernel(int N)
{
    __shared__ int warp_sums[32];
    int idx = blockIdx.x * SCAN_BLK + threadIdx.x;
    int lane = threadIdx.x & 31;
    int wid = threadIdx.x >> 5;

    int v = (idx < N) ? g_row_cnt[idx] : 0;
    int incl = v;
#pragma unroll
    for (int o = 1; o < 32; o <<= 1) {
        int n = __shfl_up_sync(0xffffffffu, incl, o);
        if (lane >= o) incl += n;
    }
    if (lane == 31) warp_sums[wid] = incl;
    __syncthreads();
    if (wid == 0) {
        int s = (lane < 32) ? warp_sums[lane] : 0;
#pragma unroll
        for (int o = 1; o < 32; o <<= 1) {
            int n = __shfl_up_sync(0xffffffffu, s, o);
            if (lane >= o) s += n;
        }
        warp_sums[lane] = s;
    }
    __syncthreads();
    int warp_base = (wid == 0) ? 0 : warp_sums[wid - 1];
    int excl = g_scan_part[blockIdx.x] + warp_base + incl - v;
    if (idx < N) {
        g_row_off[idx] = excl;
        g_row_cnt[idx] = excl;   // becomes the permute cursor
    }
}

// permute: scatter (col,val) into row-sorted list
__global__ void permute_kernel(const void* __restrict__ rows_p,
                               const void* __restrict__ cols_p,
                               const float* __restrict__ vals, int E)
{
    int e = blockIdx.x * blockDim.x + threadIdx.x;
    if (e >= E) return;
    int r = load_idx(rows_p, e);
    int c = load_idx(cols_p, e);
    unsigned int v = __float_as_uint(vals[e]);
    int pos = atomicAdd(&g_row_cnt[r], 1);
    g_edge_cv[pos] = ((unsigned long long)v << 32) | (unsigned int)c;
}

// ===========================================================================
// Gather-reduce: out[r,:] = relu( sum_e val*pre_sup[col,:] + bias )
// 16 threads per row; unrolled by 2 with dual accumulators for MLP.
// ===========================================================================
__global__ void __launch_bounds__(256) gather_kernel(
    const float* __restrict__ bias, float* __restrict__ out, int N)
{
    int r = blockIdx.x * 16 + (threadIdx.x >> 4);
    int q = threadIdx.x & 15;
    if (r >= N) return;

    int i   = g_row_off[r];
    int end = g_row_off[r + 1];

    float4 acc0 = make_float4(0.f, 0.f, 0.f, 0.f);
    float4 acc1 = make_float4(0.f, 0.f, 0.f, 0.f);
    for (; i + 2 <= end; i += 2) {
        unsigned long long cv0 = g_edge_cv[i];
        unsigned long long cv1 = g_edge_cv[i + 1];
        int c0 = (int)(unsigned int)cv0;
        int c1 = (int)(unsigned int)cv1;
        float v0 = __uint_as_float((unsigned int)(cv0 >> 32));
        float v1 = __uint_as_float((unsigned int)(cv1 >> 32));
        float4 p0 = *(const float4*)(g_pre + (size_t)c0 * N_DIM + q * 4);
        float4 p1 = *(const float4*)(g_pre + (size_t)c1 * N_DIM + q * 4);
        acc0.x = fmaf(v0, p0.x, acc0.x);
        acc0.y = fmaf(v0, p0.y, acc0.y);
        acc0.z = fmaf(v0, p0.z, acc0.z);
        acc0.w = fmaf(v0, p0.w, acc0.w);
        acc1.x = fmaf(v1, p1.x, acc1.x);
        acc1.y = fmaf(v1, p1.y, acc1.y);
        acc1.z = fmaf(v1, p1.z, acc1.z);
        acc1.w = fmaf(v1, p1.w, acc1.w);
    }
    if (i < end) {
        unsigned long long cv = g_edge_cv[i];
        int c   = (int)(unsigned int)cv;
        float v = __uint_as_float((unsigned int)(cv >> 32));
        float4 p = *(const float4*)(g_pre + (size_t)c * N_DIM + q * 4);
        acc0.x = fmaf(v, p.x, acc0.x);
        acc0.y = fmaf(v, p.y, acc0.y);
        acc0.z = fmaf(v, p.z, acc0.z);
        acc0.w = fmaf(v, p.w, acc0.w);
    }

    float4 b = *(const float4*)(bias + q * 4);
    float4 o;
    o.x = fmaxf(acc0.x + acc1.x + b.x, 0.f);
    o.y = fmaxf(acc0.y + acc1.y + b.y, 0.f);
    o.z = fmaxf(acc0.z + acc1.z + b.z, 0.f);
    o.w = fmaxf(acc0.w + acc1.w + b.w, 0.f);
    *(float4*)(out + (size_t)r * N_DIM + q * 4) = o;
}

// ===========================================================================
// Launch — GEMM kept as the 4th node (ncu captures launch #4).
// Inputs: 0:x f32[N,256]  1:rows i32/i64[E]  2:cols i32/i64[E]
//         3:vals f32[E]   4:weight f32[256,64]  5:bias f32[64]
// Output: f32 [N, 64]
// ===========================================================================
extern "C" void kernel_launch(void* const* d_in, const int* in_sizes, int n_in,
                              void* d_out, int out_size)
{
    const float* x    = (const float*)d_in[0];
    const void*  rows = d_in[1];
    const void*  cols = d_in[2];
    const float* vals = (const float*)d_in[3];
    const float* w    = (const float*)d_in[4];
    const float* bias = (const float*)d_in[5];
    float*       out  = (float*)d_out;

    const int N = in_sizes[0] / K_DIM;
    const int E = in_sizes[1];
    const int scan_blocks = (N + SCAN_BLK - 1) / SCAN_BLK;

    zero_cnt_kernel<<<(N + 1023) / 1024, 1024>>>(N);                     // 1
    detect_idx_kernel<<<1, 1024>>>((const unsigned int*)rows, E);        // 2
    hist_kernel<<<(E + 511) / 512, 512>>>(rows, E);                      // 3
    gemm_mma_kernel<<<(N + 127) / 128, 256>>>(x, w, N);                  // 4 <- profiled
    scan_partial_kernel<<<scan_blocks, SCAN_BLK>>>(N);                   // 5
    scan_base_kernel<<<1, 32>>>(scan_blocks, N);                         // 6
    scan_write_kernel<<<scan_blocks, SCAN_BLK>>>(N);                     // 7
    permute_kernel<<<(E + 511) / 512, 512>>>(rows, cols, vals, E);       // 8
    gather_kernel<<<(N + 15) / 16, 256>>>(bias, out, N);                 // 9
}

// round 10
// speedup vs baseline: 1.4718x; 1.2552x over previous
#include <cuda_runtime.h>
#include <cuda_bf16.h>
#include <cstdint>

// Problem constants (fixed by the dataset)
#define K_DIM 256
#define N_DIM 64
#define MAX_NODES 100000
#define MAX_EDGES 1310720
#define SCAN_BLK 1024
#define MAX_SCAN_BLOCKS ((MAX_NODES + SCAN_BLK - 1) / SCAN_BLK + 2)

// Device scratch (no cudaMalloc allowed)
__device__ float g_pre[(size_t)MAX_NODES * N_DIM];          // X @ W
__device__ int g_idx64;                                      // index dtype flag
__device__ int g_row_cnt[MAX_NODES];                         // counts, then cursor
__device__ int g_row_off[MAX_NODES + 1];                     // CSR offsets
__device__ unsigned long long g_edge_cv[MAX_EDGES];          // packed (val,col)
__device__ int g_scan_part[MAX_SCAN_BLOCKS];                 // scan partials

// ===========================================================================
// detect index dtype. int64 values < 2^31 have zero high words.
// ===========================================================================
__global__ void detect_idx_kernel(const unsigned int* __restrict__ rows_u32, int E)
{
    __shared__ int any_nonzero;
    if (threadIdx.x == 0) any_nonzero = 0;
    __syncthreads();
    int n = E < 4096 ? E : 4096;
    for (int i = threadIdx.x; i < n; i += blockDim.x)
        if (rows_u32[2 * i + 1] != 0u) any_nonzero = 1;   // benign smem race
    __syncthreads();
    if (threadIdx.x == 0) g_idx64 = any_nonzero ? 0 : 1;
}

__device__ __forceinline__ int load_idx(const void* p, int e)
{
    return g_idx64 ? (int)((const long long*)p)[e] : ((const int*)p)[e];
}

// ===========================================================================
// GEMM  pre_sup[M,64] = X[M,256] @ W[256,64] via tf32 mma.sync (m16n8k8),
// cp.async double-buffered: slab s+1 streams into the alternate buffer
// while slab s computes. Smem = 2x16KB X + 2x8KB W = 48KB (XOR swizzle,
// no padding). W staged raw fp32, tf32-converted at frag load (RN kept).
//
// Swizzles (conflict-free for both staging and frag reads):
//   X: xs[m][c ^ ((m&7)*4)]   (frag bank = (kt ^ 4q) -> 32 distinct lanes)
//   W: wsm[kl][n ^ ((kl&3)*8)] (frag bank = (n ^ 8t)  -> 32 distinct lanes)
// ===========================================================================
__device__ __forceinline__ uint32_t smem_u32(const void* p)
{
    uint32_t a;
    asm("{ .reg .u64 t; cvta.to.shared.u64 t, %1; cvt.u32.u64 %0, t; }"
        : "=r"(a) : "l"(p));
    return a;
}

__device__ __forceinline__ uint32_t f2tf32(float f)
{
    uint32_t r;
    asm("cvt.rna.tf32.f32 %0, %1;" : "=r"(r) : "f"(f));
    return r;
}

__device__ __forceinline__ void mma_tf32(float* d, uint32_t a0, uint32_t a1,
                                         uint32_t a2, uint32_t a3,
                                         uint32_t b0, uint32_t b1)
{
    asm volatile(
        "mma.sync.aligned.m16n8k8.row.col.f32.tf32.tf32.f32 "
        "{%0, %1, %2, %3}, {%4, %5, %6, %7}, {%8, %9}, {%0, %1, %2, %3};"
        : "+f"(d[0]), "+f"(d[1]), "+f"(d[2]), "+f"(d[3])
        : "r"(a0), "r"(a1), "r"(a2), "r"(a3), "r"(b0), "r"(b1));
}

__device__ __forceinline__ void cp_async16(uint32_t dst, const void* src, int src_bytes)
{
    asm volatile("cp.async.cg.shared.global [%0], [%1], 16, %2;"
                 :: "r"(dst), "l"(src), "r"(src_bytes) : "memory");
}

__global__ void __launch_bounds__(256, 4) gemm_mma_kernel(
    const float* __restrict__ x, const float* __restrict__ w, int M)
{
    __shared__ float xs[2][128 * 32];   // 2 x 16 KB
    __shared__ float wsm[2][32 * 64];   // 2 x  8 KB

    const int tid  = threadIdx.x;
    const int wid  = tid >> 5;
    const int lane = tid & 31;
    const int q = lane >> 2;
    const int t = lane & 3;

    const int mbase = blockIdx.x * 128;
    const int r0l = wid * 16 + q;        // local row of a0/a2
    const int r1l = r0l + 8;             // local row of a1/a3
    const int row0 = mbase + r0l;
    const int row1 = mbase + r1l;

    const uint32_t xs_base = smem_u32(&xs[0][0]);
    const uint32_t ws_base = smem_u32(&wsm[0][0]);

    // staging coordinates (constant across slabs)
    const int sm_m = (tid * 4) >> 5;            // wrong for multi-i; computed in loop
    (void)sm_m;

    float acc[8][4];
#pragma unroll
    for (int j = 0; j < 8; j++)
#pragma unroll
        for (int i = 0; i < 4; i++) acc[j][i] = 0.f;

    // ---- stage slab s into buffer buf
    auto stage = [&](int s, int buf) {
#pragma unroll
        for (int i = 0; i < 4; i++) {           // X: 1024 x 16B chunks
            int f4 = i * 256 + tid;
            int m  = f4 >> 3;                   // local row 0..127
            int c  = (f4 & 7) * 4;              // k offset in slab
            int phys = c ^ ((m & 7) * 4);
            uint32_t dst = xs_base + (uint32_t)(buf * (128 * 32) + m * 32 + phys) * 4u;
            const float* src = x + (size_t)(mbase + m) * K_DIM + s * 32 + c;
            cp_async16(dst, src, (mbase + m) < M ? 16 : 0);
        }
#pragma unroll
        for (int i = 0; i < 2; i++) {           // W: 512 x 16B chunks
            int idx = i * 256 + tid;
            int kl = idx >> 4;                  // 0..31
            int nn = (idx & 15) * 4;            // 0..60
            int physn = nn ^ ((kl & 3) * 8);
            uint32_t dst = ws_base + (uint32_t)(buf * (32 * 64) + kl * 64 + physn) * 4u;
            const float* src = w + (size_t)(s * 32 + kl) * N_DIM + nn;
            cp_async16(dst, src, 16);
        }
        asm volatile("cp.async.commit_group;" ::: "memory");
    };

    stage(0, 0);

#pragma unroll 1
    for (int s = 0; s < 8; s++) {
        if (s < 7) {
            stage(s + 1, (s + 1) & 1);
            asm volatile("cp.async.wait_group 1;" ::: "memory");
        } else {
            asm volatile("cp.async.wait_group 0;" ::: "memory");
        }
        __syncthreads();

        const float* xb = xs[s & 1];
        const float* wb = wsm[s & 1];
        const int swA = q * 4;
        const int swB = t * 8;

#pragma unroll
        for (int ks = 0; ks < 4; ks++) {
            const int kt = ks * 8 + t;
            uint32_t A0 = f2tf32(xb[r0l * 32 + (kt ^ swA)]);
            uint32_t A1 = f2tf32(xb[r1l * 32 + (kt ^ swA)]);
            uint32_t A2 = f2tf32(xb[r0l * 32 + ((kt + 4) ^ swA)]);
            uint32_t A3 = f2tf32(xb[r1l * 32 + ((kt + 4) ^ swA)]);
#pragma unroll
            for (int j = 0; j < 8; j++) {
                const int n = j * 8 + q;
                uint32_t b0 = f2tf32(wb[kt * 64 + (n ^ swB)]);
                uint32_t b1 = f2tf32(wb[(kt + 4) * 64 + (n ^ swB)]);
                mma_tf32(acc[j], A0, A1, A2, A3, b0, b1);
            }
        }
        __syncthreads();
    }

#pragma unroll
    for (int j = 0; j < 8; j++) {
        int c = j * 8 + 2 * t;
        if (row0 < M)
            *(float2*)(g_pre + (size_t)row0 * N_DIM + c) =
                make_float2(acc[j][0], acc[j][1]);
        if (row1 < M)
            *(float2*)(g_pre + (size_t)row1 * N_DIM + c) =
                make_float2(acc[j][2], acc[j][3]);
    }
}

// ===========================================================================
// CSR build
// ===========================================================================
__global__ void zero_cnt_kernel(int N)
{
    int i = blockIdx.x * blockDim.x + threadIdx.x;
    if (i < N) g_row_cnt[i] = 0;
}

__global__ void hist_kernel(const void* __restrict__ rows_p, int E)
{
    int e = blockIdx.x * blockDim.x + threadIdx.x;
    if (e >= E) return;
    atomicAdd(&g_row_cnt[load_idx(rows_p, e)], 1);
}

// scan step 1: per-block sums of counts
__global__ void __launch_bounds__(SCAN_BLK) scan_partial_kernel(int N)
{
    __shared__ int warp_sums[32];
    int idx = blockIdx.x * SCAN_BLK + threadIdx.x;
    int v = (idx < N) ? g_row_cnt[idx] : 0;
#pragma unroll
    for (int o = 16; o > 0; o >>= 1) v += __shfl_down_sync(0xffffffffu, v, o);
    if ((threadIdx.x & 31) == 0) warp_sums[threadIdx.x >> 5] = v;
    __syncthreads();
    if (threadIdx.x < 32) {
        int s = warp_sums[threadIdx.x];
#pragma unroll
        for (int o = 16; o > 0; o >>= 1) s += __shfl_down_sync(0xffffffffu, s, o);
        if (threadIdx.x == 0) g_scan_part[blockIdx.x] = s;
    }
}

// scan step 2: serial exclusive scan of block partials (tiny)
__global__ void scan_base_kernel(int nblocks, int N)
{
    if (threadIdx.x == 0 && blockIdx.x == 0) {
        int run = 0;
        for (int b = 0; b < nblocks; b++) {
            int t = g_scan_part[b];
            g_scan_part[b] = run;
            run += t;
        }
        g_row_off[N] = run;   // = E
    }
}

// scan step 3: block-local exclusive scan + base -> offsets and cursor
__global__ void __launch_bounds__(SCAN_BLK) scan_write_kernel(int N)
{
    __shared__ int warp_sums[32];
    int idx = blockIdx.x * SCAN_BLK + threadIdx.x;
    int lane = threadIdx.x & 31;
    int wid = threadIdx.x >> 5;

    int v = (idx < N) ? g_row_cnt[idx] : 0;
    int incl = v;
#pragma unroll
    for (int o = 1; o < 32; o <<= 1) {
        int n = __shfl_up_sync(0xffffffffu, incl, o);
        if (lane >= o) incl += n;
    }
    if (lane == 31) warp_sums[wid] = incl;
    __syncthreads();
    if (wid == 0) {
        int s = (lane < 32) ? warp_sums[lane] : 0;
#pragma unroll
        for (int o = 1; o < 32; o <<= 1) {
            int n = __shfl_up_sync(0xffffffffu, s, o);
            if (lane >= o) s += n;
        }
        warp_sums[lane] = s;
    }
    __syncthreads();
    int warp_base = (wid == 0) ? 0 : warp_sums[wid - 1];
    int excl = g_scan_part[blockIdx.x] + warp_base + incl - v;
    if (idx < N) {
        g_row_off[idx] = excl;
        g_row_cnt[idx] = excl;   // becomes the permute cursor
    }
}

// permute: scatter (col,val) into row-sorted list
__global__ void permute_kernel(const void* __restrict__ rows_p,
                               const void* __restrict__ cols_p,
                               const float* __restrict__ vals, int E)
{
    int e = blockIdx.x * blockDim.x + threadIdx.x;
    if (e >= E) return;
    int r = load_idx(rows_p, e);
    int c = load_idx(cols_p, e);
    unsigned int v = __float_as_uint(vals[e]);
    int pos = atomicAdd(&g_row_cnt[r], 1);
    g_edge_cv[pos] = ((unsigned long long)v << 32) | (unsigned int)c;
}

// ===========================================================================
// Gather-reduce: out[r,:] = relu( sum_e val*pre_sup[col,:] + bias )
// 16 threads per row; unrolled by 2 with dual accumulators for MLP.
// ===========================================================================
__global__ void __launch_bounds__(256) gather_kernel(
    const float* __restrict__ bias, float* __restrict__ out, int N)
{
    int r = blockIdx.x * 16 + (threadIdx.x >> 4);
    int q = threadIdx.x & 15;
    if (r >= N) return;

    int i   = g_row_off[r];
    int end = g_row_off[r + 1];

    float4 acc0 = make_float4(0.f, 0.f, 0.f, 0.f);
    float4 acc1 = make_float4(0.f, 0.f, 0.f, 0.f);
    for (; i + 2 <= end; i += 2) {
        unsigned long long cv0 = g_edge_cv[i];
        unsigned long long cv1 = g_edge_cv[i + 1];
        int c0 = (int)(unsigned int)cv0;
        int c1 = (int)(unsigned int)cv1;
        float v0 = __uint_as_float((unsigned int)(cv0 >> 32));
        float v1 = __uint_as_float((unsigned int)(cv1 >> 32));
        float4 p0 = *(const float4*)(g_pre + (size_t)c0 * N_DIM + q * 4);
        float4 p1 = *(const float4*)(g_pre + (size_t)c1 * N_DIM + q * 4);
        acc0.x = fmaf(v0, p0.x, acc0.x);
        acc0.y = fmaf(v0, p0.y, acc0.y);
        acc0.z = fmaf(v0, p0.z, acc0.z);
        acc0.w = fmaf(v0, p0.w, acc0.w);
        acc1.x = fmaf(v1, p1.x, acc1.x);
        acc1.y = fmaf(v1, p1.y, acc1.y);
        acc1.z = fmaf(v1, p1.z, acc1.z);
        acc1.w = fmaf(v1, p1.w, acc1.w);
    }
    if (i < end) {
        unsigned long long cv = g_edge_cv[i];
        int c   = (int)(unsigned int)cv;
        float v = __uint_as_float((unsigned int)(cv >> 32));
        float4 p = *(const float4*)(g_pre + (size_t)c * N_DIM + q * 4);
        acc0.x = fmaf(v, p.x, acc0.x);
        acc0.y = fmaf(v, p.y, acc0.y);
        acc0.z = fmaf(v, p.z, acc0.z);
        acc0.w = fmaf(v, p.w, acc0.w);
    }

    float4 b = *(const float4*)(bias + q * 4);
    float4 o;
    o.x = fmaxf(acc0.x + acc1.x + b.x, 0.f);
    o.y = fmaxf(acc0.y + acc1.y + b.y, 0.f);
    o.z = fmaxf(acc0.z + acc1.z + b.z, 0.f);
    o.w = fmaxf(acc0.w + acc1.w + b.w, 0.f);
    *(float4*)(out + (size_t)r * N_DIM + q * 4) = o;
}

// ===========================================================================
// Launch — GEMM kept as the 4th node (ncu captures launch #4).
// Inputs: 0:x f32[N,256]  1:rows i32/i64[E]  2:cols i32/i64[E]
//         3:vals f32[E]   4:weight f32[256,64]  5:bias f32[64]
// Output: f32 [N, 64]
// ===========================================================================
extern "C" void kernel_launch(void* const* d_in, const int* in_sizes, int n_in,
                              void* d_out, int out_size)
{
    const float* x    = (const float*)d_in[0];
    const void*  rows = d_in[1];
    const void*  cols = d_in[2];
    const float* vals = (const float*)d_in[3];
    const float* w    = (const float*)d_in[4];
    const float* bias = (const float*)d_in[5];
    float*       out  = (float*)d_out;

    const int N = in_sizes[0] / K_DIM;
    const int E = in_sizes[1];
    const int scan_blocks = (N + SCAN_BLK - 1) / SCAN_BLK;

    zero_cnt_kernel<<<(N + 1023) / 1024, 1024>>>(N);                     // 1
    detect_idx_kernel<<<1, 1024>>>((const unsigned int*)rows, E);        // 2
    hist_kernel<<<(E + 511) / 512, 512>>>(rows, E);                      // 3
    gemm_mma_kernel<<<(N + 127) / 128, 256>>>(x, w, N);                  // 4 <- profiled
    scan_partial_kernel<<<scan_blocks, SCAN_BLK>>>(N);                   // 5
    scan_base_kernel<<<1, 32>>>(scan_blocks, N);                         // 6
    scan_write_kernel<<<scan_blocks, SCAN_BLK>>>(N);                     // 7
    permute_kernel<<<(E + 511) / 512, 512>>>(rows, cols, vals, E);       // 8
    gather_kernel<<<(N + 15) / 16, 256>>>(bias, out, N);                 // 9
}

// round 11
// speedup vs baseline: 1.6209x; 1.1013x over previous
#include <cuda_runtime.h>
#include <cuda_bf16.h>
#include <cuda_fp16.h>
#include <cstdint>

// Problem constants (fixed by the dataset)
#define K_DIM 256
#define N_DIM 64
#define MAX_NODES 100000
#define MAX_EDGES 1310720
#define SCAN_BLK 1024
#define MAX_SCAN_BLOCKS ((MAX_NODES + SCAN_BLK - 1) / SCAN_BLK + 2)

// Device scratch (no cudaMalloc allowed)
__device__ uint32_t g_pre_h[(size_t)MAX_NODES * 32];        // X@W as packed half2
__device__ uint32_t g_w_tf32[K_DIM * N_DIM];                // W pre-converted to tf32
__device__ int g_idx64;                                      // index dtype flag
__device__ int g_row_cnt[MAX_NODES];                         // counts, then cursor
__device__ int g_row_off[MAX_NODES + 1];                     // CSR offsets
__device__ unsigned long long g_edge_cv[MAX_EDGES];          // packed (val,col)
__device__ int g_scan_part[MAX_SCAN_BLOCKS];                 // scan partials

// ===========================================================================
// detect index dtype. int64 values < 2^31 have zero high words.
// ===========================================================================
__global__ void detect_idx_kernel(const unsigned int* __restrict__ rows_u32, int E)
{
    __shared__ int any_nonzero;
    if (threadIdx.x == 0) any_nonzero = 0;
    __syncthreads();
    int n = E < 4096 ? E : 4096;
    for (int i = threadIdx.x; i < n; i += blockDim.x)
        if (rows_u32[2 * i + 1] != 0u) any_nonzero = 1;   // benign smem race
    __syncthreads();
    if (threadIdx.x == 0) g_idx64 = any_nonzero ? 0 : 1;
}

__device__ __forceinline__ int load_idx(const void* p, int e)
{
    return g_idx64 ? (int)((const long long*)p)[e] : ((const int*)p)[e];
}

// ===========================================================================
// W pre-convert: fp32 -> tf32 bit pattern, once for the whole grid.
// ===========================================================================
__device__ __forceinline__ uint32_t f2tf32(float f)
{
    uint32_t r;
    asm("cvt.rna.tf32.f32 %0, %1;" : "=r"(r) : "f"(f));
    return r;
}

__global__ void wconv_kernel(const float* __restrict__ w)
{
    int i = blockIdx.x * blockDim.x + threadIdx.x;
    if (i < K_DIM * N_DIM) g_w_tf32[i] = f2tf32(w[i]);
}

// ===========================================================================
// GEMM  pre_sup[M,64] = X[M,256] @ W[256,64] via tf32 mma.sync (m16n8k8),
// cp.async double-buffered. W staged already-tf32 (wconv_kernel) -> B frag
// load is a bare LDS (R10 profile: alu 30% from 16x per-kstep f2tf32 on B).
// Output stored as packed half2 (halves gather L2 traffic).
//
// Swizzles (conflict-free for staging and frag reads):
//   X: xs[m][c ^ ((m&7)*4)]    W: wsm[kl][n ^ ((kl&3)*8)]
// ===========================================================================
__device__ __forceinline__ uint32_t smem_u32(const void* p)
{
    uint32_t a;
    asm("{ .reg .u64 t; cvta.to.shared.u64 t, %1; cvt.u32.u64 %0, t; }"
        : "=r"(a) : "l"(p));
    return a;
}

__device__ __forceinline__ void mma_tf32(float* d, uint32_t a0, uint32_t a1,
                                         uint32_t a2, uint32_t a3,
                                         uint32_t b0, uint32_t b1)
{
    asm volatile(
        "mma.sync.aligned.m16n8k8.row.col.f32.tf32.tf32.f32 "
        "{%0, %1, %2, %3}, {%4, %5, %6, %7}, {%8, %9}, {%0, %1, %2, %3};"
        : "+f"(d[0]), "+f"(d[1]), "+f"(d[2]), "+f"(d[3])
        : "r"(a0), "r"(a1), "r"(a2), "r"(a3), "r"(b0), "r"(b1));
}

__device__ __forceinline__ void cp_async16(uint32_t dst, const void* src, int src_bytes)
{
    asm volatile("cp.async.cg.shared.global [%0], [%1], 16, %2;"
                 :: "r"(dst), "l"(src), "r"(src_bytes) : "memory");
}

__global__ void __launch_bounds__(256, 4) gemm_mma_kernel(
    const float* __restrict__ x, int M)
{
    __shared__ float    xs[2][128 * 32];   // 2 x 16 KB
    __shared__ uint32_t wsm[2][32 * 64];   // 2 x  8 KB (tf32 bits)

    const int tid  = threadIdx.x;
    const int wid  = tid >> 5;
    const int lane = tid & 31;
    const int q = lane >> 2;
    const int t = lane & 3;

    const int mbase = blockIdx.x * 128;
    const int r0l = wid * 16 + q;
    const int r1l = r0l + 8;
    const int row0 = mbase + r0l;
    const int row1 = mbase + r1l;

    const uint32_t xs_base = smem_u32(&xs[0][0]);
    const uint32_t ws_base = smem_u32(&wsm[0][0]);

    float acc[8][4];
#pragma unroll
    for (int j = 0; j < 8; j++)
#pragma unroll
        for (int i = 0; i < 4; i++) acc[j][i] = 0.f;

    auto stage = [&](int s, int buf) {
#pragma unroll
        for (int i = 0; i < 4; i++) {           // X: 1024 x 16B chunks
            int f4 = i * 256 + tid;
            int m  = f4 >> 3;
            int c  = (f4 & 7) * 4;
            int phys = c ^ ((m & 7) * 4);
            uint32_t dst = xs_base + (uint32_t)(buf * (128 * 32) + m * 32 + phys) * 4u;
            const float* src = x + (size_t)(mbase + m) * K_DIM + s * 32 + c;
            cp_async16(dst, src, (mbase + m) < M ? 16 : 0);
        }
#pragma unroll
        for (int i = 0; i < 2; i++) {           // W: 512 x 16B chunks (tf32)
            int idx = i * 256 + tid;
            int kl = idx >> 4;
            int nn = (idx & 15) * 4;
            int physn = nn ^ ((kl & 3) * 8);
            uint32_t dst = ws_base + (uint32_t)(buf * (32 * 64) + kl * 64 + physn) * 4u;
            const uint32_t* src = g_w_tf32 + (size_t)(s * 32 + kl) * N_DIM + nn;
            cp_async16(dst, src, 16);
        }
        asm volatile("cp.async.commit_group;" ::: "memory");
    };

    stage(0, 0);

#pragma unroll 1
    for (int s = 0; s < 8; s++) {
        if (s < 7) {
            stage(s + 1, (s + 1) & 1);
            asm volatile("cp.async.wait_group 1;" ::: "memory");
        } else {
            asm volatile("cp.async.wait_group 0;" ::: "memory");
        }
        __syncthreads();

        const float*    xb = xs[s & 1];
        const uint32_t* wb = wsm[s & 1];
        const int swA = q * 4;
        const int swB = t * 8;

#pragma unroll
        for (int ks = 0; ks < 4; ks++) {
            const int kt = ks * 8 + t;
            uint32_t A0 = f2tf32(xb[r0l * 32 + (kt ^ swA)]);
            uint32_t A1 = f2tf32(xb[r1l * 32 + (kt ^ swA)]);
            uint32_t A2 = f2tf32(xb[r0l * 32 + ((kt + 4) ^ swA)]);
            uint32_t A3 = f2tf32(xb[r1l * 32 + ((kt + 4) ^ swA)]);
#pragma unroll
            for (int j = 0; j < 8; j++) {
                const int n = j * 8 + q;
                uint32_t b0 = wb[kt * 64 + (n ^ swB)];
                uint32_t b1 = wb[(kt + 4) * 64 + (n ^ swB)];
                mma_tf32(acc[j], A0, A1, A2, A3, b0, b1);
            }
        }
        __syncthreads();
    }

    // ---- epilogue: pack adjacent cols (2t, 2t+1) into half2
#pragma unroll
    for (int j = 0; j < 8; j++) {
        int h_idx = j * 4 + t;    // half2 index = (j*8 + 2t) / 2
        if (row0 < M) {
            __half2 h = __float22half2_rn(make_float2(acc[j][0], acc[j][1]));
            g_pre_h[(size_t)row0 * 32 + h_idx] = *(uint32_t*)&h;
        }
        if (row1 < M) {
            __half2 h = __float22half2_rn(make_float2(acc[j][2], acc[j][3]));
            g_pre_h[(size_t)row1 * 32 + h_idx] = *(uint32_t*)&h;
        }
    }
}

// ===========================================================================
// CSR build
// ===========================================================================
__global__ void zero_cnt_kernel(int N)
{
    int i = blockIdx.x * blockDim.x + threadIdx.x;
    if (i < N) g_row_cnt[i] = 0;
}

__global__ void hist_kernel(const void* __restrict__ rows_p, int E)
{
    int e = blockIdx.x * blockDim.x + threadIdx.x;
    if (e >= E) return;
    atomicAdd(&g_row_cnt[load_idx(rows_p, e)], 1);
}

// scan step 1: per-block sums of counts
__global__ void __launch_bounds__(SCAN_BLK) scan_partial_kernel(int N)
{
    __shared__ int warp_sums[32];
    int idx = blockIdx.x * SCAN_BLK + threadIdx.x;
    int v = (idx < N) ? g_row_cnt[idx] : 0;
#pragma unroll
    for (int o = 16; o > 0; o >>= 1) v += __shfl_down_sync(0xffffffffu, v, o);
    if ((threadIdx.x & 31) == 0) warp_sums[threadIdx.x >> 5] = v;
    __syncthreads();
    if (threadIdx.x < 32) {
        int s = warp_sums[threadIdx.x];
#pragma unroll
        for (int o = 16; o > 0; o >>= 1) s += __shfl_down_sync(0xffffffffu, s, o);
        if (threadIdx.x == 0) g_scan_part[blockIdx.x] = s;
    }
}

// scan step 2: serial exclusive scan of block partials (tiny)
__global__ void scan_base_kernel(int nblocks, int N)
{
    if (threadIdx.x == 0 && blockIdx.x == 0) {
        int run = 0;
        for (int b = 0; b < nblocks; b++) {
            int t = g_scan_part[b];
            g_scan_part[b] = run;
            run += t;
        }
        g_row_off[N] = run;   // = E
    }
}

// scan step 3: block-local exclusive scan + base -> offsets and cursor
__global__ void __launch_bounds__(SCAN_BLK) scan_write_kernel(int N)
{
    __shared__ int warp_sums[32];
    int idx = blockIdx.x * SCAN_BLK + threadIdx.x;
    int lane = threadIdx.x & 31;
    int wid = threadIdx.x >> 5;

    int v = (idx < N) ? g_row_cnt[idx] : 0;
    int incl = v;
#pragma unroll
    for (int o = 1; o < 32; o <<= 1) {
        int n = __shfl_up_sync(0xffffffffu, incl, o);
        if (lane >= o) incl += n;
    }
    if (lane == 31) warp_sums[wid] = incl;
    __syncthreads();
    if (wid == 0) {
        int s = (lane < 32) ? warp_sums[lane] : 0;
#pragma unroll
        for (int o = 1; o < 32; o <<= 1) {
            int n = __shfl_up_sync(0xffffffffu, s, o);
            if (lane >= o) s += n;
        }
        warp_sums[lane] = s;
    }
    __syncthreads();
    int warp_base = (wid == 0) ? 0 : warp_sums[wid - 1];
    int excl = g_scan_part[blockIdx.x] + warp_base + incl - v;
    if (idx < N) {
        g_row_off[idx] = excl;
        g_row_cnt[idx] = excl;   // becomes the permute cursor
    }
}

// permute: scatter (col,val) into row-sorted list
__global__ void permute_kernel(const void* __restrict__ rows_p,
                               const void* __restrict__ cols_p,
                               const float* __restrict__ vals, int E)
{
    int e = blockIdx.x * blockDim.x + threadIdx.x;
    if (e >= E) return;
    int r = load_idx(rows_p, e);
    int c = load_idx(cols_p, e);
    unsigned int v = __float_as_uint(vals[e]);
    int pos = atomicAdd(&g_row_cnt[r], 1);
    g_edge_cv[pos] = ((unsigned long long)v << 32) | (unsigned int)c;
}

// ===========================================================================
// Gather-reduce: out[r,:] = relu( sum_e val*pre_sup[col,:] + bias )
// 16 threads per row; pre_sup is packed half2 (8B per quad per edge).
// ===========================================================================
__global__ void __launch_bounds__(256) gather_kernel(
    const float* __restrict__ bias, float* __restrict__ out, int N)
{
    int r = blockIdx.x * 16 + (threadIdx.x >> 4);
    int q = threadIdx.x & 15;
    if (r >= N) return;

    int i   = g_row_off[r];
    int end = g_row_off[r + 1];

    float4 acc0 = make_float4(0.f, 0.f, 0.f, 0.f);
    float4 acc1 = make_float4(0.f, 0.f, 0.f, 0.f);
    for (; i + 2 <= end; i += 2) {
        unsigned long long cv0 = g_edge_cv[i];
        unsigned long long cv1 = g_edge_cv[i + 1];
        int c0 = (int)(unsigned int)cv0;
        int c1 = (int)(unsigned int)cv1;
        float v0 = __uint_as_float((unsigned int)(cv0 >> 32));
        float v1 = __uint_as_float((unsigned int)(cv1 >> 32));
        uint2 u0 = *(const uint2*)(g_pre_h + (size_t)c0 * 32 + q * 2);
        uint2 u1 = *(const uint2*)(g_pre_h + (size_t)c1 * 32 + q * 2);
        float2 p0a = __half22float2(*(__half2*)&u0.x);
        float2 p0b = __half22float2(*(__half2*)&u0.y);
        float2 p1a = __half22float2(*(__half2*)&u1.x);
        float2 p1b = __half22float2(*(__half2*)&u1.y);
        acc0.x = fmaf(v0, p0a.x, acc0.x);
        acc0.y = fmaf(v0, p0a.y, acc0.y);
        acc0.z = fmaf(v0, p0b.x, acc0.z);
        acc0.w = fmaf(v0, p0b.y, acc0.w);
        acc1.x = fmaf(v1, p1a.x, acc1.x);
        acc1.y = fmaf(v1, p1a.y, acc1.y);
        acc1.z = fmaf(v1, p1b.x, acc1.z);
        acc1.w = fmaf(v1, p1b.y, acc1.w);
    }
    if (i < end) {
        unsigned long long cv = g_edge_cv[i];
        int c   = (int)(unsigned int)cv;
        float v = __uint_as_float((unsigned int)(cv >> 32));
        uint2 u = *(const uint2*)(g_pre_h + (size_t)c * 32 + q * 2);
        float2 pa = __half22float2(*(__half2*)&u.x);
        float2 pb = __half22float2(*(__half2*)&u.y);
        acc0.x = fmaf(v, pa.x, acc0.x);
        acc0.y = fmaf(v, pa.y, acc0.y);
        acc0.z = fmaf(v, pb.x, acc0.z);
        acc0.w = fmaf(v, pb.y, acc0.w);
    }

    float4 b = *(const float4*)(bias + q * 4);
    float4 o;
    o.x = fmaxf(acc0.x + acc1.x + b.x, 0.f);
    o.y = fmaxf(acc0.y + acc1.y + b.y, 0.f);
    o.z = fmaxf(acc0.z + acc1.z + b.z, 0.f);
    o.w = fmaxf(acc0.w + acc1.w + b.w, 0.f);
    *(float4*)(out + (size_t)r * N_DIM + q * 4) = o;
}

// ===========================================================================
// Launch — GEMM kept as the 4th node (ncu captures launch #4).
// Inputs: 0:x f32[N,256]  1:rows i32/i64[E]  2:cols i32/i64[E]
//         3:vals f32[E]   4:weight f32[256,64]  5:bias f32[64]
// Output: f32 [N, 64]
// ===========================================================================
extern "C" void kernel_launch(void* const* d_in, const int* in_sizes, int n_in,
                              void* d_out, int out_size)
{
    const float* x    = (const float*)d_in[0];
    const void*  rows = d_in[1];
    const void*  cols = d_in[2];
    const float* vals = (const float*)d_in[3];
    const float* w    = (const float*)d_in[4];
    const float* bias = (const float*)d_in[5];
    float*       out  = (float*)d_out;

    const int N = in_sizes[0] / K_DIM;
    const int E = in_sizes[1];
    const int scan_blocks = (N + SCAN_BLK - 1) / SCAN_BLK;

    zero_cnt_kernel<<<(N + 1023) / 1024, 1024>>>(N);                     // 1
    wconv_kernel<<<(K_DIM * N_DIM + 255) / 256, 256>>>(w);               // 2
    detect_idx_kernel<<<1, 1024>>>((const unsigned int*)rows, E);        // 3
    gemm_mma_kernel<<<(N + 127) / 128, 256>>>(x, N);                     // 4 <- profiled
    hist_kernel<<<(E + 511) / 512, 512>>>(rows, E);                      // 5
    scan_partial_kernel<<<scan_blocks, SCAN_BLK>>>(N);                   // 6
    scan_base_kernel<<<1, 32>>>(scan_blocks, N);                         // 7
    scan_write_kernel<<<scan_blocks, SCAN_BLK>>>(N);                     // 8
    permute_kernel<<<(E + 511) / 512, 512>>>(rows, cols, vals, E);       // 9
    gather_kernel<<<(N + 15) / 16, 256>>>(bias, out, N);                 // 10
}

// round 12
// speedup vs baseline: 1.8163x; 1.1206x over previous
#include <cuda_runtime.h>
#include <cuda_bf16.h>
#include <cuda_fp16.h>
#include <cstdint>

// Problem constants (fixed by the dataset)
#define K_DIM 256
#define N_DIM 64
#define MAX_NODES 100000
#define MAX_EDGES 1310720
#define SCAN_BLK 1024
#define MAX_SCAN_BLOCKS ((MAX_NODES + SCAN_BLK - 1) / SCAN_BLK + 2)

// Device scratch (no cudaMalloc allowed)
__device__ uint32_t g_pre_h[(size_t)MAX_NODES * 32];        // X@W as packed half2
__device__ uint32_t g_w_tf32[K_DIM * N_DIM];                // W pre-converted to tf32
__device__ int g_idx64;                                      // index dtype flag
__device__ int g_row_cnt[MAX_NODES];                         // counts, then cursor
__device__ int g_row_off[MAX_NODES + 1];                     // CSR offsets
__device__ unsigned long long g_edge_cv[MAX_EDGES];          // packed (val,col)
__device__ int g_scan_part[MAX_SCAN_BLOCKS];                 // scan partials

__device__ __forceinline__ int load_idx(const void* p, int e)
{
    return g_idx64 ? (int)((const long long*)p)[e] : ((const int*)p)[e];
}

__device__ __forceinline__ uint32_t f2tf32(float f)
{
    uint32_t r;
    asm("cvt.rna.tf32.f32 %0, %1;" : "=r"(r) : "f"(f));
    return r;
}

// ===========================================================================
// Fused init: block 0 = index-dtype detect (block-internal, no race);
// blocks [1, zb] = zero g_row_cnt; blocks (zb, ...] = W fp32->tf32.
// ===========================================================================
__global__ void fused_init_kernel(const float* __restrict__ w,
                                  const unsigned int* __restrict__ rows_u32,
                                  int N, int E, int zb)
{
    int b = blockIdx.x;
    if (b == 0) {
        __shared__ int any;
        if (threadIdx.x == 0) any = 0;
        __syncthreads();
        int n = E < 4096 ? E : 4096;
        for (int i = threadIdx.x; i < n; i += 256)
            if (rows_u32[2 * i + 1] != 0u) any = 1;   // benign smem race
        __syncthreads();
        if (threadIdx.x == 0) g_idx64 = any ? 0 : 1;
    } else if (b <= zb) {
        int i = (b - 1) * 256 + threadIdx.x;
        if (i < N) g_row_cnt[i] = 0;
    } else {
        int i = (b - 1 - zb) * 256 + threadIdx.x;
        if (i < K_DIM * N_DIM) g_w_tf32[i] = f2tf32(w[i]);
    }
}

// ===========================================================================
// Fused GEMM + histogram. Blocks [0, GB): tf32 mma.sync GEMM tile (cp.async
// double-buffered, unchanged from R11). Blocks [GB, ...): row histogram —
// they backfill SMs as GEMM CTAs retire, hiding hist AND the GEMM tail wave.
// ===========================================================================
__device__ __forceinline__ uint32_t smem_u32(const void* p)
{
    uint32_t a;
    asm("{ .reg .u64 t; cvta.to.shared.u64 t, %1; cvt.u32.u64 %0, t; }"
        : "=r"(a) : "l"(p));
    return a;
}

__device__ __forceinline__ void mma_tf32(float* d, uint32_t a0, uint32_t a1,
                                         uint32_t a2, uint32_t a3,
                                         uint32_t b0, uint32_t b1)
{
    asm volatile(
        "mma.sync.aligned.m16n8k8.row.col.f32.tf32.tf32.f32 "
        "{%0, %1, %2, %3}, {%4, %5, %6, %7}, {%8, %9}, {%0, %1, %2, %3};"
        : "+f"(d[0]), "+f"(d[1]), "+f"(d[2]), "+f"(d[3])
        : "r"(a0), "r"(a1), "r"(a2), "r"(a3), "r"(b0), "r"(b1));
}

__device__ __forceinline__ void cp_async16(uint32_t dst, const void* src, int src_bytes)
{
    asm volatile("cp.async.cg.shared.global [%0], [%1], 16, %2;"
                 :: "r"(dst), "l"(src), "r"(src_bytes) : "memory");
}

__global__ void __launch_bounds__(256, 4) gemm_hist_kernel(
    const float* __restrict__ x, const void* __restrict__ rows_p,
    int M, int GB, int E)
{
    __shared__ float    xs[2][128 * 32];   // 2 x 16 KB
    __shared__ uint32_t wsm[2][32 * 64];   // 2 x  8 KB (tf32 bits)

    // ---- histogram blocks
    if ((int)blockIdx.x >= GB) {
        int e = ((int)blockIdx.x - GB) * 256 + threadIdx.x;
        if (e < E) atomicAdd(&g_row_cnt[load_idx(rows_p, e)], 1);
        return;
    }

    // ---- GEMM blocks
    const int tid  = threadIdx.x;
    const int wid  = tid >> 5;
    const int lane = tid & 31;
    const int q = lane >> 2;
    const int t = lane & 3;

    const int mbase = blockIdx.x * 128;
    const int r0l = wid * 16 + q;
    const int r1l = r0l + 8;
    const int row0 = mbase + r0l;
    const int row1 = mbase + r1l;

    const uint32_t xs_base = smem_u32(&xs[0][0]);
    const uint32_t ws_base = smem_u32(&wsm[0][0]);

    float acc[8][4];
#pragma unroll
    for (int j = 0; j < 8; j++)
#pragma unroll
        for (int i = 0; i < 4; i++) acc[j][i] = 0.f;

    auto stage = [&](int s, int buf) {
#pragma unroll
        for (int i = 0; i < 4; i++) {           // X: 1024 x 16B chunks
            int f4 = i * 256 + tid;
            int m  = f4 >> 3;
            int c  = (f4 & 7) * 4;
            int phys = c ^ ((m & 7) * 4);
            uint32_t dst = xs_base + (uint32_t)(buf * (128 * 32) + m * 32 + phys) * 4u;
            const float* src = x + (size_t)(mbase + m) * K_DIM + s * 32 + c;
            cp_async16(dst, src, (mbase + m) < M ? 16 : 0);
        }
#pragma unroll
        for (int i = 0; i < 2; i++) {           // W: 512 x 16B chunks (tf32)
            int idx = i * 256 + tid;
            int kl = idx >> 4;
            int nn = (idx & 15) * 4;
            int physn = nn ^ ((kl & 3) * 8);
            uint32_t dst = ws_base + (uint32_t)(buf * (32 * 64) + kl * 64 + physn) * 4u;
            const uint32_t* src = g_w_tf32 + (size_t)(s * 32 + kl) * N_DIM + nn;
            cp_async16(dst, src, 16);
        }
        asm volatile("cp.async.commit_group;" ::: "memory");
    };

    stage(0, 0);

#pragma unroll 1
    for (int s = 0; s < 8; s++) {
        if (s < 7) {
            stage(s + 1, (s + 1) & 1);
            asm volatile("cp.async.wait_group 1;" ::: "memory");
        } else {
            asm volatile("cp.async.wait_group 0;" ::: "memory");
        }
        __syncthreads();

        const float*    xb = xs[s & 1];
        const uint32_t* wb = wsm[s & 1];
        const int swA = q * 4;
        const int swB = t * 8;

#pragma unroll
        for (int ks = 0; ks < 4; ks++) {
            const int kt = ks * 8 + t;
            uint32_t A0 = f2tf32(xb[r0l * 32 + (kt ^ swA)]);
            uint32_t A1 = f2tf32(xb[r1l * 32 + (kt ^ swA)]);
            uint32_t A2 = f2tf32(xb[r0l * 32 + ((kt + 4) ^ swA)]);
            uint32_t A3 = f2tf32(xb[r1l * 32 + ((kt + 4) ^ swA)]);
#pragma unroll
            for (int j = 0; j < 8; j++) {
                const int n = j * 8 + q;
                uint32_t b0 = wb[kt * 64 + (n ^ swB)];
                uint32_t b1 = wb[(kt + 4) * 64 + (n ^ swB)];
                mma_tf32(acc[j], A0, A1, A2, A3, b0, b1);
            }
        }
        __syncthreads();
    }

    // ---- epilogue: pack adjacent cols (2t, 2t+1) into half2
#pragma unroll
    for (int j = 0; j < 8; j++) {
        int h_idx = j * 4 + t;
        if (row0 < M) {
            __half2 h = __float22half2_rn(make_float2(acc[j][0], acc[j][1]));
            g_pre_h[(size_t)row0 * 32 + h_idx] = *(uint32_t*)&h;
        }
        if (row1 < M) {
            __half2 h = __float22half2_rn(make_float2(acc[j][2], acc[j][3]));
            g_pre_h[(size_t)row1 * 32 + h_idx] = *(uint32_t*)&h;
        }
    }
}

// ===========================================================================
// Scan (3 phases) over g_row_cnt -> g_row_off (+ cursor reset)
// ===========================================================================
__global__ void __launch_bounds__(SCAN_BLK) scan_partial_kernel(int N)
{
    __shared__ int warp_sums[32];
    int idx = blockIdx.x * SCAN_BLK + threadIdx.x;
    int v = (idx < N) ? g_row_cnt[idx] : 0;
#pragma unroll
    for (int o = 16; o > 0; o >>= 1) v += __shfl_down_sync(0xffffffffu, v, o);
    if ((threadIdx.x & 31) == 0) warp_sums[threadIdx.x >> 5] = v;
    __syncthreads();
    if (threadIdx.x < 32) {
        int s = warp_sums[threadIdx.x];
#pragma unroll
        for (int o = 16; o > 0; o >>= 1) s += __shfl_down_sync(0xffffffffu, s, o);
        if (threadIdx.x == 0) g_scan_part[blockIdx.x] = s;
    }
}

// single block, 128 threads: parallel exclusive scan of block partials
__global__ void scan_base_kernel(int nblocks, int N)
{
    __shared__ int ws[4];
    int lane = threadIdx.x & 31;
    int wid  = threadIdx.x >> 5;
    int v = (threadIdx.x < nblocks) ? g_scan_part[threadIdx.x] : 0;
    int incl = v;
#pragma unroll
    for (int o = 1; o < 32; o <<= 1) {
        int n = __shfl_up_sync(0xffffffffu, incl, o);
        if (lane >= o) incl += n;
    }
    if (lane == 31) ws[wid] = incl;
    __syncthreads();
    if (wid == 0 && lane < 4) {
        int s = ws[lane];
#pragma unroll
        for (int o = 1; o < 4; o <<= 1) {
            int n = __shfl_up_sync(0x0000000fu, s, o);
            if (lane >= o) s += n;
        }
        ws[lane] = s;
    }
    __syncthreads();
    int base = (wid == 0) ? 0 : ws[wid - 1];
    if (threadIdx.x < nblocks) g_scan_part[threadIdx.x] = base + incl - v;
    if (threadIdx.x == 0) g_row_off[N] = ws[3];   // total = E
}

__global__ void __launch_bounds__(SCAN_BLK) scan_write_kernel(int N)
{
    __shared__ int warp_sums[32];
    int idx = blockIdx.x * SCAN_BLK + threadIdx.x;
    int lane = threadIdx.x & 31;
    int wid = threadIdx.x >> 5;

    int v = (idx < N) ? g_row_cnt[idx] : 0;
    int incl = v;
#pragma unroll
    for (int o = 1; o < 32; o <<= 1) {
        int n = __shfl_up_sync(0xffffffffu, incl, o);
        if (lane >= o) incl += n;
    }
    if (lane == 31) warp_sums[wid] = incl;
    __syncthreads();
    if (wid == 0) {
        int s = (lane < 32) ? warp_sums[lane] : 0;
#pragma unroll
        for (int o = 1; o < 32; o <<= 1) {
            int n = __shfl_up_sync(0xffffffffu, s, o);
            if (lane >= o) s += n;
        }
        warp_sums[lane] = s;
    }
    __syncthreads();
    int warp_base = (wid == 0) ? 0 : warp_sums[wid - 1];
    int excl = g_scan_part[blockIdx.x] + warp_base + incl - v;
    if (idx < N) {
        g_row_off[idx] = excl;
        g_row_cnt[idx] = excl;   // becomes the permute cursor
    }
}

// permute: scatter (col,val) into row-sorted list
__global__ void permute_kernel(const void* __restrict__ rows_p,
                               const void* __restrict__ cols_p,
                               const float* __restrict__ vals, int E)
{
    int e = blockIdx.x * blockDim.x + threadIdx.x;
    if (e >= E) return;
    int r = load_idx(rows_p, e);
    int c = load_idx(cols_p, e);
    unsigned int v = __float_as_uint(vals[e]);
    int pos = atomicAdd(&g_row_cnt[r], 1);
    g_edge_cv[pos] = ((unsigned long long)v << 32) | (unsigned int)c;
}

// ===========================================================================
// Gather-reduce: out[r,:] = relu( sum_e val*pre_sup[col,:] + bias )
// 16 threads per row; pre_sup is packed half2 (8B per quad per edge).
// ===========================================================================
__global__ void __launch_bounds__(256) gather_kernel(
    const float* __restrict__ bias, float* __restrict__ out, int N)
{
    int r = blockIdx.x * 16 + (threadIdx.x >> 4);
    int q = threadIdx.x & 15;
    if (r >= N) return;

    int i   = g_row_off[r];
    int end = g_row_off[r + 1];

    float4 acc0 = make_float4(0.f, 0.f, 0.f, 0.f);
    float4 acc1 = make_float4(0.f, 0.f, 0.f, 0.f);
    for (; i + 2 <= end; i += 2) {
        unsigned long long cv0 = g_edge_cv[i];
        unsigned long long cv1 = g_edge_cv[i + 1];
        int c0 = (int)(unsigned int)cv0;
        int c1 = (int)(unsigned int)cv1;
        float v0 = __uint_as_float((unsigned int)(cv0 >> 32));
        float v1 = __uint_as_float((unsigned int)(cv1 >> 32));
        uint2 u0 = *(const uint2*)(g_pre_h + (size_t)c0 * 32 + q * 2);
        uint2 u1 = *(const uint2*)(g_pre_h + (size_t)c1 * 32 + q * 2);
        float2 p0a = __half22float2(*(__half2*)&u0.x);
        float2 p0b = __half22float2(*(__half2*)&u0.y);
        float2 p1a = __half22float2(*(__half2*)&u1.x);
        float2 p1b = __half22float2(*(__half2*)&u1.y);
        acc0.x = fmaf(v0, p0a.x, acc0.x);
        acc0.y = fmaf(v0, p0a.y, acc0.y);
        acc0.z = fmaf(v0, p0b.x, acc0.z);
        acc0.w = fmaf(v0, p0b.y, acc0.w);
        acc1.x = fmaf(v1, p1a.x, acc1.x);
        acc1.y = fmaf(v1, p1a.y, acc1.y);
        acc1.z = fmaf(v1, p1b.x, acc1.z);
        acc1.w = fmaf(v1, p1b.y, acc1.w);
    }
    if (i < end) {
        unsigned long long cv = g_edge_cv[i];
        int c   = (int)(unsigned int)cv;
        float v = __uint_as_float((unsigned int)(cv >> 32));
        uint2 u = *(const uint2*)(g_pre_h + (size_t)c * 32 + q * 2);
        float2 pa = __half22float2(*(__half2*)&u.x);
        float2 pb = __half22float2(*(__half2*)&u.y);
        acc0.x = fmaf(v, pa.x, acc0.x);
        acc0.y = fmaf(v, pa.y, acc0.y);
        acc0.z = fmaf(v, pb.x, acc0.z);
        acc0.w = fmaf(v, pb.y, acc0.w);
    }

    float4 b = *(const float4*)(bias + q * 4);
    float4 o;
    o.x = fmaxf(acc0.x + acc1.x + b.x, 0.f);
    o.y = fmaxf(acc0.y + acc1.y + b.y, 0.f);
    o.z = fmaxf(acc0.z + acc1.z + b.z, 0.f);
    o.w = fmaxf(acc0.w + acc1.w + b.w, 0.f);
    *(float4*)(out + (size_t)r * N_DIM + q * 4) = o;
}

// ===========================================================================
// Launch
// Inputs: 0:x f32[N,256]  1:rows i32/i64[E]  2:cols i32/i64[E]
//         3:vals f32[E]   4:weight f32[256,64]  5:bias f32[64]
// Output: f32 [N, 64]
// ===========================================================================
extern "C" void kernel_launch(void* const* d_in, const int* in_sizes, int n_in,
                              void* d_out, int out_size)
{
    const float* x    = (const float*)d_in[0];
    const void*  rows = d_in[1];
    const void*  cols = d_in[2];
    const float* vals = (const float*)d_in[3];
    const float* w    = (const float*)d_in[4];
    const float* bias = (const float*)d_in[5];
    float*       out  = (float*)d_out;

    const int N = in_sizes[0] / K_DIM;
    const int E = in_sizes[1];
    const int scan_blocks = (N + SCAN_BLK - 1) / SCAN_BLK;
    const int zb = (N + 255) / 256;                 // zero blocks
    const int wb = (K_DIM * N_DIM + 255) / 256;     // wconv blocks
    const int GB = (N + 127) / 128;                 // gemm blocks
    const int HB = (E + 255) / 256;                 // hist blocks

    fused_init_kernel<<<1 + zb + wb, 256>>>(w, (const unsigned int*)rows, N, E, zb);
    gemm_hist_kernel<<<GB + HB, 256>>>(x, rows, N, GB, E);
    scan_partial_kernel<<<scan_blocks, SCAN_BLK>>>(N);
    scan_base_kernel<<<1, 128>>>(scan_blocks, N);
    scan_write_kernel<<<scan_blocks, SCAN_BLK>>>(N);
    permute_kernel<<<(E + 511) / 512, 512>>>(rows, cols, vals, E);
    gather_kernel<<<(N + 15) / 16, 256>>>(bias, out, N);
}